// round 1
// baseline (speedup 1.0000x reference)
#include <cuda_runtime.h>
#include <math.h>

#define Bsz 2
#define Tsz 2048
#define Csz 1024
#define NH 16
#define NKV 4
#define NGROUP 4
#define HD 64
#define Mrows (Bsz*Tsz)      // 4096
#define KVC (NKV*HD)         // 256

// Scratch (device globals: no allocation allowed in kernel_launch)
__device__ float g_q [Mrows*Csz];   // [B*T, 1024]  q projection (RoPE'd in place)
__device__ float g_k [Mrows*KVC];   // [B*T, 256]
__device__ float g_v [Mrows*KVC];   // [B*T, 256]
__device__ float g_ao[Mrows*Csz];   // attention output [B*T, 1024]

// ---------------------------------------------------------------------------
// GEMM: C[M,N] = A[M,K] @ W[K,N] + bias[N]
// BM=128, BN=64, BK=16, 256 threads, each thread computes 8x4.
// ---------------------------------------------------------------------------
__global__ __launch_bounds__(256)
void gemm_bias_kernel(const float* __restrict__ A,
                      const float* __restrict__ W,
                      const float* __restrict__ bias,
                      float* __restrict__ Cmat,
                      int M, int K, int N)
{
    const int BM = 128, BN = 64, BK = 16;
    __shared__ float As[BK][BM + 4];   // k-major (transposed A tile)
    __shared__ float Bs[BK][BN];

    int tid = threadIdx.x;
    int tx = tid & 15;        // 0..15 -> 4 output cols
    int ty = tid >> 4;        // 0..15 -> 8 output rows
    int m0 = blockIdx.y * BM;
    int n0 = blockIdx.x * BN;

    float acc[8][4];
#pragma unroll
    for (int i = 0; i < 8; i++)
#pragma unroll
        for (int j = 0; j < 4; j++) acc[i][j] = 0.f;

    for (int k0 = 0; k0 < K; k0 += BK) {
        // A tile: 128 x 16 = 512 float4, 2 per thread
#pragma unroll
        for (int p = 0; p < 2; p++) {
            int i4 = tid + p * 256;
            int r  = i4 >> 2;       // 0..127
            int c4 = i4 & 3;        // 0..3
            float4 t = *(const float4*)(A + (size_t)(m0 + r) * K + k0 + c4 * 4);
            As[c4*4 + 0][r] = t.x;
            As[c4*4 + 1][r] = t.y;
            As[c4*4 + 2][r] = t.z;
            As[c4*4 + 3][r] = t.w;
        }
        // B tile: 16 x 64 = 256 float4, 1 per thread
        {
            int r  = tid >> 4;      // 0..15
            int c4 = tid & 15;      // 0..15
            *(float4*)&Bs[r][c4*4] =
                *(const float4*)(W + (size_t)(k0 + r) * N + n0 + c4 * 4);
        }
        __syncthreads();

#pragma unroll
        for (int kk = 0; kk < BK; kk++) {
            float a[8], bv[4];
            *(float4*)(a)     = *(const float4*)&As[kk][ty*8];
            *(float4*)(a + 4) = *(const float4*)&As[kk][ty*8 + 4];
            *(float4*)(bv)    = *(const float4*)&Bs[kk][tx*4];
#pragma unroll
            for (int i = 0; i < 8; i++)
#pragma unroll
                for (int j = 0; j < 4; j++)
                    acc[i][j] = fmaf(a[i], bv[j], acc[i][j]);
        }
        __syncthreads();
    }

    float4 bb = *(const float4*)(bias + n0 + tx*4);
#pragma unroll
    for (int i = 0; i < 8; i++) {
        float4 r4;
        r4.x = acc[i][0] + bb.x;
        r4.y = acc[i][1] + bb.y;
        r4.z = acc[i][2] + bb.z;
        r4.w = acc[i][3] + bb.w;
        *(float4*)(Cmat + (size_t)(m0 + ty*8 + i) * N + n0 + tx*4) = r4;
    }
}

// ---------------------------------------------------------------------------
// RoPE (interleaved pairs), in place. One thread per (row, head, pair).
// ---------------------------------------------------------------------------
__global__ void rope_kernel(float* __restrict__ t, int nheads, int total_pairs)
{
    int idx = blockIdx.x * blockDim.x + threadIdx.x;
    if (idx >= total_pairs) return;
    int pair = idx & 31;           // 0..31
    int rem  = idx >> 5;
    int h    = rem % nheads;
    int row  = rem / nheads;       // 0..Mrows-1
    int tpos = row & (Tsz - 1);    // row % T

    float inv = powf(10000.0f, -(float)(2 * pair) / (float)HD);
    float th  = (float)tpos * inv;
    float sn, cs;
    sincosf(th, &sn, &cs);

    float* base = t + ((size_t)row * nheads + h) * HD + pair * 2;
    float e = base[0], o = base[1];
    base[0] = e * cs - o * sn;
    base[1] = e * sn + o * cs;
}

// ---------------------------------------------------------------------------
// Flash attention (fp32). Block: 64 q-rows x one head. 256 threads, 4x4 tiles.
// Streams 64-key tiles; causal blocks above the diagonal are skipped.
// ---------------------------------------------------------------------------
__global__ __launch_bounds__(256)
void attn_kernel(const float* __restrict__ q,
                 const float* __restrict__ k,
                 const float* __restrict__ v,
                 float* __restrict__ o)
{
    extern __shared__ float sm[];
    float* Qst = sm;                 // [64][68]  d-major  (Qst[d][r])
    float* Kst = Qst + 64 * 68;      // [64][68]  d-major  (Kst[d][c])
    float* Vs  = Kst + 64 * 68;      // [64][68]  key-major (Vs[kk][c])
    float* Pst = Vs  + 64 * 68;      // [64][68]  key-major (Pst[kk][r])

    int b  = blockIdx.z;
    int h  = blockIdx.y;
    int qb = blockIdx.x;
    int q0 = qb * 64;
    int kvh = h >> 2;                // h / NGROUP

    int tid = threadIdx.x;
    int tx  = tid & 15;              // 4 score-cols / out-dims
    int ty  = tid >> 4;              // 4 rows

    // load Q tile transposed, pre-scaled by 1/sqrt(HD)
    {
        const float* qbase = q + (size_t)(b * Tsz + q0) * Csz + h * HD;
#pragma unroll
        for (int p = 0; p < 4; p++) {
            int i4 = tid + p * 256;     // 0..1023
            int r  = i4 >> 4;           // 0..63
            int c4 = i4 & 15;           // 0..15
            float4 t4 = *(const float4*)(qbase + (size_t)r * Csz + c4 * 4);
            Qst[(c4*4 + 0) * 68 + r] = t4.x * 0.125f;
            Qst[(c4*4 + 1) * 68 + r] = t4.y * 0.125f;
            Qst[(c4*4 + 2) * 68 + r] = t4.z * 0.125f;
            Qst[(c4*4 + 3) * 68 + r] = t4.w * 0.125f;
        }
    }

    float acc[4][4];
    float mrow[4], lrow[4];
#pragma unroll
    for (int i = 0; i < 4; i++) {
        mrow[i] = -1e30f; lrow[i] = 0.f;
#pragma unroll
        for (int j = 0; j < 4; j++) acc[i][j] = 0.f;
    }

    for (int kb = 0; kb <= qb; kb++) {
        __syncthreads();   // also covers Q-load on first iter; protects Ks/Vs reuse after
        // load K (transposed) and V (key-major) tiles
        const float* kbase = k + (size_t)(b * Tsz + kb * 64) * KVC + kvh * HD;
        const float* vbase = v + (size_t)(b * Tsz + kb * 64) * KVC + kvh * HD;
#pragma unroll
        for (int p = 0; p < 4; p++) {
            int i4 = tid + p * 256;
            int r  = i4 >> 4;
            int c4 = i4 & 15;
            float4 t4 = *(const float4*)(kbase + (size_t)r * KVC + c4 * 4);
            Kst[(c4*4 + 0) * 68 + r] = t4.x;
            Kst[(c4*4 + 1) * 68 + r] = t4.y;
            Kst[(c4*4 + 2) * 68 + r] = t4.z;
            Kst[(c4*4 + 3) * 68 + r] = t4.w;
            float4 u4 = *(const float4*)(vbase + (size_t)r * KVC + c4 * 4);
            *(float4*)(Vs + r * 68 + c4 * 4) = u4;
        }
        __syncthreads();

        // scores S = Q K^T
        float s[4][4];
#pragma unroll
        for (int i = 0; i < 4; i++)
#pragma unroll
            for (int j = 0; j < 4; j++) s[i][j] = 0.f;
#pragma unroll 8
        for (int d = 0; d < HD; d++) {
            float av[4], bv[4];
            *(float4*)av = *(const float4*)(Qst + d * 68 + ty * 4);
            *(float4*)bv = *(const float4*)(Kst + d * 68 + tx * 4);
#pragma unroll
            for (int i = 0; i < 4; i++)
#pragma unroll
                for (int j = 0; j < 4; j++)
                    s[i][j] = fmaf(av[i], bv[j], s[i][j]);
        }

        if (kb == qb) {
#pragma unroll
            for (int i = 0; i < 4; i++)
#pragma unroll
                for (int j = 0; j < 4; j++)
                    if (tx * 4 + j > ty * 4 + i) s[i][j] = -1e30f;
        }

        // streaming softmax update (row groups = 16 lanes sharing ty bit)
#pragma unroll
        for (int i = 0; i < 4; i++) {
            float rm = fmaxf(fmaxf(s[i][0], s[i][1]), fmaxf(s[i][2], s[i][3]));
#pragma unroll
            for (int off = 8; off > 0; off >>= 1)
                rm = fmaxf(rm, __shfl_xor_sync(0xffffffffu, rm, off));
            float mnew = fmaxf(mrow[i], rm);
            float corr = __expf(mrow[i] - mnew);
            mrow[i] = mnew;
            lrow[i] *= corr;
            float psum = 0.f;
#pragma unroll
            for (int j = 0; j < 4; j++) {
                float pv = __expf(s[i][j] - mnew);
                s[i][j] = pv;
                psum += pv;
            }
#pragma unroll
            for (int off = 8; off > 0; off >>= 1)
                psum += __shfl_xor_sync(0xffffffffu, psum, off);
            lrow[i] += psum;
#pragma unroll
            for (int j = 0; j < 4; j++) acc[i][j] *= corr;
        }

        // stage P transposed: Pst[kk][r]
#pragma unroll
        for (int j = 0; j < 4; j++) {
            *(float4*)(Pst + (size_t)(tx * 4 + j) * 68 + ty * 4) =
                make_float4(s[0][j], s[1][j], s[2][j], s[3][j]);
        }
        __syncthreads();

        // O += P V
#pragma unroll 8
        for (int kk = 0; kk < 64; kk++) {
            float av[4], bv[4];
            *(float4*)av = *(const float4*)(Pst + kk * 68 + ty * 4);
            *(float4*)bv = *(const float4*)(Vs  + kk * 68 + tx * 4);
#pragma unroll
            for (int i = 0; i < 4; i++)
#pragma unroll
                for (int j = 0; j < 4; j++)
                    acc[i][j] = fmaf(av[i], bv[j], acc[i][j]);
        }
    }

    // epilogue: normalize and store [B*T, C] at head offset
    float* obase = o + (size_t)(b * Tsz + q0) * Csz + h * HD;
#pragma unroll
    for (int i = 0; i < 4; i++) {
        float inv = 1.0f / lrow[i];
        float4 r4 = make_float4(acc[i][0] * inv, acc[i][1] * inv,
                                acc[i][2] * inv, acc[i][3] * inv);
        *(float4*)(obase + (size_t)(ty * 4 + i) * Csz + tx * 4) = r4;
    }
}

// ---------------------------------------------------------------------------
extern "C" void kernel_launch(void* const* d_in, const int* in_sizes, int n_in,
                              void* d_out, int out_size)
{
    const float* x   = (const float*)d_in[0];
    const float* w_q = (const float*)d_in[1];
    const float* b_q = (const float*)d_in[2];
    const float* w_k = (const float*)d_in[3];
    const float* b_k = (const float*)d_in[4];
    const float* w_v = (const float*)d_in[5];
    const float* b_v = (const float*)d_in[6];
    const float* w_o = (const float*)d_in[7];
    const float* b_o = (const float*)d_in[8];
    float* out = (float*)d_out;

    float *q, *k, *v, *ao;
    cudaGetSymbolAddress((void**)&q,  g_q);
    cudaGetSymbolAddress((void**)&k,  g_k);
    cudaGetSymbolAddress((void**)&v,  g_v);
    cudaGetSymbolAddress((void**)&ao, g_ao);

    // QKV projections
    gemm_bias_kernel<<<dim3(Csz/64, Mrows/128), 256>>>(x, w_q, b_q, q, Mrows, Csz, Csz);
    gemm_bias_kernel<<<dim3(KVC/64, Mrows/128), 256>>>(x, w_k, b_k, k, Mrows, Csz, KVC);
    gemm_bias_kernel<<<dim3(KVC/64, Mrows/128), 256>>>(x, w_v, b_v, v, Mrows, Csz, KVC);

    // RoPE
    {
        int nq = Mrows * NH * (HD / 2);
        rope_kernel<<<(nq + 255) / 256, 256>>>(q, NH, nq);
        int nk = Mrows * NKV * (HD / 2);
        rope_kernel<<<(nk + 255) / 256, 256>>>(k, NKV, nk);
    }

    // Flash attention
    {
        int smem = 4 * 64 * 68 * (int)sizeof(float);   // 69632 B
        cudaFuncSetAttribute(attn_kernel, cudaFuncAttributeMaxDynamicSharedMemorySize, smem);
        attn_kernel<<<dim3(Tsz/64, NH, Bsz), 256, smem>>>(q, k, v, ao);
    }

    // output projection
    gemm_bias_kernel<<<dim3(Csz/64, Mrows/128), 256>>>(ao, w_o, b_o, out, Mrows, Csz, Csz);
}

// round 2
// speedup vs baseline: 1.9954x; 1.9954x over previous
#include <cuda_runtime.h>
#include <math.h>
#include <stdint.h>

#define Bsz 2
#define Tsz 2048
#define Csz 1024
#define NH 16
#define NKV 4
#define HD 64
#define Mrows (Bsz*Tsz)      // 4096
#define KVC (NKV*HD)         // 256
#define QB 128               // q rows per attention CTA

// Scratch (device globals: no allocation allowed)
__device__ float g_q [Mrows*Csz];
__device__ float g_k [Mrows*KVC];
__device__ float g_v [Mrows*KVC];
__device__ float g_ao[Mrows*Csz];

__device__ __forceinline__ float tf32r(float x) {
    uint32_t u; asm("cvt.rna.tf32.f32 %0, %1;" : "=r"(u) : "f"(x));
    return __uint_as_float(u);
}

__device__ __forceinline__ void mma_tf32(float c[4], const uint32_t a[4], const uint32_t b[2]) {
    asm volatile(
        "mma.sync.aligned.m16n8k8.row.col.f32.tf32.tf32.f32 "
        "{%0,%1,%2,%3}, {%4,%5,%6,%7}, {%8,%9}, {%0,%1,%2,%3};\n"
        : "+f"(c[0]), "+f"(c[1]), "+f"(c[2]), "+f"(c[3])
        : "r"(a[0]), "r"(a[1]), "r"(a[2]), "r"(a[3]), "r"(b[0]), "r"(b[1]));
}

// ---------------------------------------------------------------------------
// tf32 tensor-core GEMM: C[M,N] = A[M,K] @ W[K,N] + bias
// Block 128x64, BK=16, 8 warps in 4(m) x 2(n), warp tile 32x32.
// ---------------------------------------------------------------------------
__global__ __launch_bounds__(256)
void gemm_tf32(const float* __restrict__ A, const float* __restrict__ W,
               const float* __restrict__ bias, float* __restrict__ C,
               int M, int K, int N)
{
    __shared__ float As[16][136];   // k-major: As[k][m]; bank = 8*tig+g -> conflict-free
    __shared__ float Bs[16][72];    // Bs[k][n]

    int tid = threadIdx.x;
    int lane = tid & 31, w = tid >> 5;
    int g = lane >> 2, tg = lane & 3;
    int wm = (w & 3) * 32, wn = (w >> 2) * 32;
    int m0 = blockIdx.y * 128, n0 = blockIdx.x * 64;

    float acc[2][4][4] = {};

    for (int k0 = 0; k0 < K; k0 += 16) {
        // A tile 128x16 (512 float4, 2 per thread) -> transposed, tf32-rounded
#pragma unroll
        for (int p = 0; p < 2; p++) {
            int i4 = tid + p * 256;
            int r = i4 >> 2, c4 = i4 & 3;
            float4 t = *(const float4*)(A + (size_t)(m0 + r) * K + k0 + c4 * 4);
            As[c4*4+0][r] = tf32r(t.x);
            As[c4*4+1][r] = tf32r(t.y);
            As[c4*4+2][r] = tf32r(t.z);
            As[c4*4+3][r] = tf32r(t.w);
        }
        // B tile 16x64 (256 float4, 1 per thread)
        {
            int r = tid >> 4, c4 = tid & 15;
            float4 t = *(const float4*)(W + (size_t)(k0 + r) * N + n0 + c4 * 4);
            float4 u = make_float4(tf32r(t.x), tf32r(t.y), tf32r(t.z), tf32r(t.w));
            *(float4*)&Bs[r][c4*4] = u;
        }
        __syncthreads();

#pragma unroll
        for (int ks = 0; ks < 2; ks++) {
            uint32_t af[2][4], bf[4][2];
#pragma unroll
            for (int mt = 0; mt < 2; mt++) {
                int mr = wm + mt * 16;
                af[mt][0] = __float_as_uint(As[ks*8+tg  ][mr+g  ]);
                af[mt][1] = __float_as_uint(As[ks*8+tg  ][mr+g+8]);
                af[mt][2] = __float_as_uint(As[ks*8+tg+4][mr+g  ]);
                af[mt][3] = __float_as_uint(As[ks*8+tg+4][mr+g+8]);
            }
#pragma unroll
            for (int nt = 0; nt < 4; nt++) {
                bf[nt][0] = __float_as_uint(Bs[ks*8+tg  ][wn+nt*8+g]);
                bf[nt][1] = __float_as_uint(Bs[ks*8+tg+4][wn+nt*8+g]);
            }
#pragma unroll
            for (int mt = 0; mt < 2; mt++)
#pragma unroll
                for (int nt = 0; nt < 4; nt++)
                    mma_tf32(acc[mt][nt], af[mt], bf[nt]);
        }
        __syncthreads();
    }

#pragma unroll
    for (int mt = 0; mt < 2; mt++) {
        int r0 = m0 + wm + mt * 16 + g;
#pragma unroll
        for (int nt = 0; nt < 4; nt++) {
            int c = n0 + wn + nt * 8 + tg * 2;
            float2 bb = *(const float2*)(bias + c);
            float2 v0 = make_float2(acc[mt][nt][0] + bb.x, acc[mt][nt][1] + bb.y);
            float2 v1 = make_float2(acc[mt][nt][2] + bb.x, acc[mt][nt][3] + bb.y);
            *(float2*)(C + (size_t)r0 * N + c)       = v0;
            *(float2*)(C + (size_t)(r0 + 8) * N + c) = v1;
        }
    }
}

// ---------------------------------------------------------------------------
// RoPE (interleaved pairs), in place.
// ---------------------------------------------------------------------------
__global__ void rope_kernel(float* __restrict__ t, int nheads, int total_pairs)
{
    int idx = blockIdx.x * blockDim.x + threadIdx.x;
    if (idx >= total_pairs) return;
    int pair = idx & 31;
    int rem  = idx >> 5;
    int h    = rem % nheads;
    int row  = rem / nheads;
    int tpos = row & (Tsz - 1);

    float inv = powf(10000.0f, -(float)(2 * pair) / (float)HD);
    float th  = (float)tpos * inv;
    float sn, cs;
    sincosf(th, &sn, &cs);

    float* base = t + ((size_t)row * nheads + h) * HD + pair * 2;
    float e = base[0], o = base[1];
    base[0] = e * cs - o * sn;
    base[1] = e * sn + o * cs;
}

// ---------------------------------------------------------------------------
// Flash attention, tf32 tensor cores.
// CTA: 128 q-rows x 1 head. 8 warps = 4(m) x 2(n); warp tile 32 rows x 32 cols.
// Streams 64-key tiles. Cross-warp softmax via smem (m,sum) exchange.
// ---------------------------------------------------------------------------
__global__ __launch_bounds__(256)
void attn_tf32(const float* __restrict__ q, const float* __restrict__ k,
               const float* __restrict__ v, float* __restrict__ o)
{
    extern __shared__ float sm[];
    float (*Qs)[68] = (float(*)[68])sm;                          // [128][68]
    float (*Ks)[72] = (float(*)[72])(sm + QB*68);                // [64][72]  d-major
    float (*Vs)[72] = (float(*)[72])(sm + QB*68 + 64*72);        // [64][72]  key-major
    float (*Ps)[68] = (float(*)[68])(sm + QB*68 + 2*64*72);      // [128][68]
    float2* red     = (float2*)(sm + 2*QB*68 + 2*64*72);         // [128][2]

    int b  = blockIdx.z;
    int h  = blockIdx.y;
    int qb = gridDim.x - 1 - blockIdx.x;   // heavy blocks first
    int q0 = qb * QB;
    int kvh = h >> 2;

    int tid = threadIdx.x;
    int lane = tid & 31, w = tid >> 5;
    int g = lane >> 2, tg = lane & 3;
    int wm = (w >> 1) * 32;    // warp row origin (0,32,64,96)
    int wn = w & 1;            // warp col half (0,1)

    // load Q tile (pre-scaled by 1/8, tf32-rounded)
    {
        const float* qbase = q + (size_t)(b * Tsz + q0) * Csz + h * HD;
#pragma unroll
        for (int p = 0; p < 8; p++) {
            int i4 = tid + p * 256;
            int r = i4 >> 4, c4 = i4 & 15;
            float4 t = *(const float4*)(qbase + (size_t)r * Csz + c4 * 4);
            float4 u = make_float4(tf32r(t.x * 0.125f), tf32r(t.y * 0.125f),
                                   tf32r(t.z * 0.125f), tf32r(t.w * 0.125f));
            *(float4*)&Qs[r][c4*4] = u;
        }
    }

    float mrun[2][2], lrun[2][2];
    float oacc[2][4][4] = {};
#pragma unroll
    for (int mt = 0; mt < 2; mt++)
#pragma unroll
        for (int ri = 0; ri < 2; ri++) { mrun[mt][ri] = -1e30f; lrun[mt][ri] = 0.f; }

    int kb_max = 2 * qb + 1;
    for (int kb = 0; kb <= kb_max; kb++) {
        __syncthreads();   // protects Qs (first iter), Ks/Vs/Ps/red reuse
        // load K (d-major) and V (key-major) tiles, tf32-rounded
        const float* kp = k + (size_t)(b * Tsz + kb * 64) * KVC + kvh * HD;
        const float* vp = v + (size_t)(b * Tsz + kb * 64) * KVC + kvh * HD;
#pragma unroll
        for (int p = 0; p < 4; p++) {
            int idx = tid + p * 256;
            int key = idx & 63, c4 = idx >> 6;
            float4 t = *(const float4*)(kp + (size_t)key * KVC + c4 * 4);
            Ks[c4*4+0][key] = tf32r(t.x);
            Ks[c4*4+1][key] = tf32r(t.y);
            Ks[c4*4+2][key] = tf32r(t.z);
            Ks[c4*4+3][key] = tf32r(t.w);
            float4 u = *(const float4*)(vp + (size_t)key * KVC + c4 * 4);
            float4 uu = make_float4(tf32r(u.x), tf32r(u.y), tf32r(u.z), tf32r(u.w));
            *(float4*)&Vs[key][c4*4] = uu;
        }
        __syncthreads();

        // S = Q K^T  (warp tile 32x32, k over d=64)
        float s[2][4][4] = {};
#pragma unroll
        for (int ks = 0; ks < 8; ks++) {
            uint32_t af[2][4], bf[4][2];
#pragma unroll
            for (int mt = 0; mt < 2; mt++) {
                int mr = wm + mt * 16;
                af[mt][0] = __float_as_uint(Qs[mr+g  ][ks*8+tg  ]);
                af[mt][1] = __float_as_uint(Qs[mr+g+8][ks*8+tg  ]);
                af[mt][2] = __float_as_uint(Qs[mr+g  ][ks*8+tg+4]);
                af[mt][3] = __float_as_uint(Qs[mr+g+8][ks*8+tg+4]);
            }
#pragma unroll
            for (int nt = 0; nt < 4; nt++) {
                bf[nt][0] = __float_as_uint(Ks[ks*8+tg  ][wn*32+nt*8+g]);
                bf[nt][1] = __float_as_uint(Ks[ks*8+tg+4][wn*32+nt*8+g]);
            }
#pragma unroll
            for (int mt = 0; mt < 2; mt++)
#pragma unroll
                for (int nt = 0; nt < 4; nt++)
                    mma_tf32(s[mt][nt], af[mt], bf[nt]);
        }

        // causal mask (only near the diagonal)
        if (kb >= 2 * qb) {
#pragma unroll
            for (int mt = 0; mt < 2; mt++) {
                int row0 = q0 + wm + mt * 16 + g;
#pragma unroll
                for (int nt = 0; nt < 4; nt++) {
                    int col = kb * 64 + wn * 32 + nt * 8 + 2 * tg;
                    if (col     > row0    ) s[mt][nt][0] = -1e30f;
                    if (col + 1 > row0    ) s[mt][nt][1] = -1e30f;
                    if (col     > row0 + 8) s[mt][nt][2] = -1e30f;
                    if (col + 1 > row0 + 8) s[mt][nt][3] = -1e30f;
                }
            }
        }

        // per-warp-half row max + exp + sum
        float mh[2][2], sh[2][2];
#pragma unroll
        for (int mt = 0; mt < 2; mt++)
#pragma unroll
            for (int ri = 0; ri < 2; ri++) {
                float mx = -1e30f;
#pragma unroll
                for (int nt = 0; nt < 4; nt++) {
                    mx = fmaxf(mx, s[mt][nt][2*ri]);
                    mx = fmaxf(mx, s[mt][nt][2*ri+1]);
                }
                mx = fmaxf(mx, __shfl_xor_sync(0xffffffffu, mx, 1));
                mx = fmaxf(mx, __shfl_xor_sync(0xffffffffu, mx, 2));
                float sum = 0.f;
#pragma unroll
                for (int nt = 0; nt < 4; nt++) {
                    float p0 = __expf(s[mt][nt][2*ri]   - mx);
                    float p1 = __expf(s[mt][nt][2*ri+1] - mx);
                    s[mt][nt][2*ri] = p0; s[mt][nt][2*ri+1] = p1;
                    sum += p0 + p1;
                }
                sum += __shfl_xor_sync(0xffffffffu, sum, 1);
                sum += __shfl_xor_sync(0xffffffffu, sum, 2);
                mh[mt][ri] = mx; sh[mt][ri] = sum;
            }

        if (tg == 0) {
#pragma unroll
            for (int mt = 0; mt < 2; mt++)
#pragma unroll
                for (int ri = 0; ri < 2; ri++)
                    red[(wm + mt*16 + ri*8 + g) * 2 + wn] = make_float2(mh[mt][ri], sh[mt][ri]);
        }
        __syncthreads();

        // combine halves, rescale O, write P to smem
#pragma unroll
        for (int mt = 0; mt < 2; mt++)
#pragma unroll
            for (int ri = 0; ri < 2; ri++) {
                int rl = wm + mt*16 + ri*8 + g;
                float2 r0 = red[rl*2 + 0];
                float2 r1 = red[rl*2 + 1];
                float mold = mrun[mt][ri];
                float mnew = fmaxf(mold, fmaxf(r0.x, r1.x));
                float corr = __expf(mold - mnew);
                lrun[mt][ri] = lrun[mt][ri] * corr
                             + r0.y * __expf(r0.x - mnew)
                             + r1.y * __expf(r1.x - mnew);
                mrun[mt][ri] = mnew;
                float pscale = __expf(mh[mt][ri] - mnew);
#pragma unroll
                for (int nt = 0; nt < 4; nt++) {
                    oacc[mt][nt][2*ri]   *= corr;
                    oacc[mt][nt][2*ri+1] *= corr;
                    float p0 = tf32r(s[mt][nt][2*ri]   * pscale);
                    float p1 = tf32r(s[mt][nt][2*ri+1] * pscale);
                    *(float2*)&Ps[rl][wn*32 + nt*8 + 2*tg] = make_float2(p0, p1);
                }
            }
        __syncthreads();

        // O += P V   (k over 64 keys)
#pragma unroll
        for (int ks = 0; ks < 8; ks++) {
            uint32_t af[2][4], bf[4][2];
#pragma unroll
            for (int mt = 0; mt < 2; mt++) {
                int mr = wm + mt * 16;
                af[mt][0] = __float_as_uint(Ps[mr+g  ][ks*8+tg  ]);
                af[mt][1] = __float_as_uint(Ps[mr+g+8][ks*8+tg  ]);
                af[mt][2] = __float_as_uint(Ps[mr+g  ][ks*8+tg+4]);
                af[mt][3] = __float_as_uint(Ps[mr+g+8][ks*8+tg+4]);
            }
#pragma unroll
            for (int nt = 0; nt < 4; nt++) {
                bf[nt][0] = __float_as_uint(Vs[ks*8+tg  ][wn*32+nt*8+g]);
                bf[nt][1] = __float_as_uint(Vs[ks*8+tg+4][wn*32+nt*8+g]);
            }
#pragma unroll
            for (int mt = 0; mt < 2; mt++)
#pragma unroll
                for (int nt = 0; nt < 4; nt++)
                    mma_tf32(oacc[mt][nt], af[mt], bf[nt]);
        }
    }

    // epilogue: normalize + store
    float* obase = o + (size_t)(b * Tsz + q0) * Csz + h * HD;
#pragma unroll
    for (int mt = 0; mt < 2; mt++)
#pragma unroll
        for (int ri = 0; ri < 2; ri++) {
            int rl = wm + mt*16 + ri*8 + g;
            float inv = 1.0f / lrun[mt][ri];
#pragma unroll
            for (int nt = 0; nt < 4; nt++) {
                float2 r2 = make_float2(oacc[mt][nt][2*ri] * inv, oacc[mt][nt][2*ri+1] * inv);
                *(float2*)(obase + (size_t)rl * Csz + wn*32 + nt*8 + 2*tg) = r2;
            }
        }
}

// ---------------------------------------------------------------------------
extern "C" void kernel_launch(void* const* d_in, const int* in_sizes, int n_in,
                              void* d_out, int out_size)
{
    const float* x   = (const float*)d_in[0];
    const float* w_q = (const float*)d_in[1];
    const float* b_q = (const float*)d_in[2];
    const float* w_k = (const float*)d_in[3];
    const float* b_k = (const float*)d_in[4];
    const float* w_v = (const float*)d_in[5];
    const float* b_v = (const float*)d_in[6];
    const float* w_o = (const float*)d_in[7];
    const float* b_o = (const float*)d_in[8];
    float* out = (float*)d_out;

    float *q, *k, *v, *ao;
    cudaGetSymbolAddress((void**)&q,  g_q);
    cudaGetSymbolAddress((void**)&k,  g_k);
    cudaGetSymbolAddress((void**)&v,  g_v);
    cudaGetSymbolAddress((void**)&ao, g_ao);

    gemm_tf32<<<dim3(Csz/64, Mrows/128), 256>>>(x, w_q, b_q, q, Mrows, Csz, Csz);
    gemm_tf32<<<dim3(KVC/64, Mrows/128), 256>>>(x, w_k, b_k, k, Mrows, Csz, KVC);
    gemm_tf32<<<dim3(KVC/64, Mrows/128), 256>>>(x, w_v, b_v, v, Mrows, Csz, KVC);

    {
        int nq = Mrows * NH * (HD / 2);
        rope_kernel<<<(nq + 255) / 256, 256>>>(q, NH, nq);
        int nk = Mrows * NKV * (HD / 2);
        rope_kernel<<<(nk + 255) / 256, 256>>>(k, NKV, nk);
    }

    {
        int smem = (2*QB*68 + 2*64*72 + QB*4) * (int)sizeof(float);  // 108544
        cudaFuncSetAttribute(attn_tf32, cudaFuncAttributeMaxDynamicSharedMemorySize, smem);
        attn_tf32<<<dim3(Tsz/QB, NH, Bsz), 256, smem>>>(q, k, v, ao);
    }

    gemm_tf32<<<dim3(Csz/64, Mrows/128), 256>>>(ao, w_o, b_o, out, Mrows, Csz, Csz);
}

// round 4
// speedup vs baseline: 2.0959x; 1.0504x over previous
#include <cuda_runtime.h>
#include <math.h>
#include <stdint.h>

#define Bsz 2
#define Tsz 2048
#define Csz 1024
#define NH 16
#define NKV 4
#define HD 64
#define Mrows (Bsz*Tsz)      // 4096
#define KVC (NKV*HD)         // 256
#define QB 128               // q rows per attention CTA

// Scratch (device globals: no allocation allowed)
__device__ float g_q [Mrows*Csz];
__device__ float g_k [Mrows*KVC];
__device__ float g_v [Mrows*KVC];
__device__ float g_ao[Mrows*Csz];

__device__ __forceinline__ float tf32r(float x) {
    uint32_t u; asm("cvt.rna.tf32.f32 %0, %1;" : "=r"(u) : "f"(x));
    return __uint_as_float(u);
}

__device__ __forceinline__ void mma_tf32(float c[4], const uint32_t a[4], const uint32_t b[2]) {
    asm volatile(
        "mma.sync.aligned.m16n8k8.row.col.f32.tf32.tf32.f32 "
        "{%0,%1,%2,%3}, {%4,%5,%6,%7}, {%8,%9}, {%0,%1,%2,%3};\n"
        : "+f"(c[0]), "+f"(c[1]), "+f"(c[2]), "+f"(c[3])
        : "r"(a[0]), "r"(a[1]), "r"(a[2]), "r"(a[3]), "r"(b[0]), "r"(b[1]));
}

// ---------------------------------------------------------------------------
// tf32 tensor-core GEMM (R2-proven smem layout + fragment indexing),
// with register double-buffering of the next BK=16 tile.
// C[M,N] = A[M,K] @ W[K,N] + bias ; optional fused interleaved RoPE.
// Block 128x64, BK=16, 8 warps 4(m)x2(n), warp tile 32x32.
// ---------------------------------------------------------------------------
template<bool DO_ROPE>
__global__ __launch_bounds__(256)
void gemm_tf32(const float* __restrict__ A, const float* __restrict__ W,
               const float* __restrict__ bias, float* __restrict__ C,
               int M, int K, int N)
{
    __shared__ float As[16][136];   // k-major: As[k][m]  (R2 layout)
    __shared__ float Bs[16][72];    // Bs[k][n]

    int tid = threadIdx.x;
    int lane = tid & 31, w = tid >> 5;
    int g = lane >> 2, tg = lane & 3;
    int wm = (w & 3) * 32, wn = (w >> 2) * 32;
    int m0 = blockIdx.y * 128, n0 = blockIdx.x * 64;

    // per-thread load geometry (identical to R2's)
    int ar0 = tid >> 2, ar1 = (tid + 256) >> 2, ac4 = tid & 3;   // A rows, col-chunk
    int br  = tid >> 4, bc4 = tid & 15;                          // B row, col-chunk

    float acc[2][4][4] = {};
    float4 areg0, areg1, breg;

    auto ldt = [&](int k0) {
        areg0 = *(const float4*)(A + (size_t)(m0 + ar0) * K + k0 + ac4 * 4);
        areg1 = *(const float4*)(A + (size_t)(m0 + ar1) * K + k0 + ac4 * 4);
        breg  = *(const float4*)(W + (size_t)(k0 + br) * N + n0 + bc4 * 4);
    };

    int niter = K / 16;
    ldt(0);

    for (int i = 0; i < niter; i++) {
        __syncthreads();   // previous tile fully consumed
        // stage registers -> smem (R2's exact store pattern, tf32-rounded)
        As[ac4*4+0][ar0] = tf32r(areg0.x);
        As[ac4*4+1][ar0] = tf32r(areg0.y);
        As[ac4*4+2][ar0] = tf32r(areg0.z);
        As[ac4*4+3][ar0] = tf32r(areg0.w);
        As[ac4*4+0][ar1] = tf32r(areg1.x);
        As[ac4*4+1][ar1] = tf32r(areg1.y);
        As[ac4*4+2][ar1] = tf32r(areg1.z);
        As[ac4*4+3][ar1] = tf32r(areg1.w);
        {
            float4 u = make_float4(tf32r(breg.x), tf32r(breg.y),
                                   tf32r(breg.z), tf32r(breg.w));
            *(float4*)&Bs[br][bc4*4] = u;
        }
        __syncthreads();

        if (i + 1 < niter) ldt((i + 1) * 16);   // overlap next tile's LDGs

        // compute (R2's exact fragment indexing)
#pragma unroll
        for (int ks = 0; ks < 2; ks++) {
            uint32_t af[2][4], bf[4][2];
#pragma unroll
            for (int mt = 0; mt < 2; mt++) {
                int mr = wm + mt * 16;
                af[mt][0] = __float_as_uint(As[ks*8+tg  ][mr+g  ]);
                af[mt][1] = __float_as_uint(As[ks*8+tg  ][mr+g+8]);
                af[mt][2] = __float_as_uint(As[ks*8+tg+4][mr+g  ]);
                af[mt][3] = __float_as_uint(As[ks*8+tg+4][mr+g+8]);
            }
#pragma unroll
            for (int nt = 0; nt < 4; nt++) {
                bf[nt][0] = __float_as_uint(Bs[ks*8+tg  ][wn+nt*8+g]);
                bf[nt][1] = __float_as_uint(Bs[ks*8+tg+4][wn+nt*8+g]);
            }
#pragma unroll
            for (int mt = 0; mt < 2; mt++)
#pragma unroll
                for (int nt = 0; nt < 4; nt++)
                    mma_tf32(acc[mt][nt], af[mt], bf[nt]);
        }
    }

    // epilogue: bias (+ optional interleaved RoPE), store
#pragma unroll
    for (int mt = 0; mt < 2; mt++) {
        int r0 = m0 + wm + mt * 16 + g;
#pragma unroll
        for (int nt = 0; nt < 4; nt++) {
            int c = n0 + wn + nt * 8 + tg * 2;
            float2 bb = *(const float2*)(bias + c);
            float2 v0 = make_float2(acc[mt][nt][0] + bb.x, acc[mt][nt][1] + bb.y);
            float2 v1 = make_float2(acc[mt][nt][2] + bb.x, acc[mt][nt][3] + bb.y);
            if (DO_ROPE) {
                int pair = (c & (HD - 1)) >> 1;
                float inv = powf(10000.0f, -(float)(2 * pair) / (float)HD);
                float sn0, cs0, sn1, cs1;
                sincosf((float)(r0 & (Tsz - 1)) * inv, &sn0, &cs0);
                sincosf((float)((r0 + 8) & (Tsz - 1)) * inv, &sn1, &cs1);
                float e0 = v0.x, o0 = v0.y;
                v0.x = e0 * cs0 - o0 * sn0;  v0.y = e0 * sn0 + o0 * cs0;
                float e1 = v1.x, o1 = v1.y;
                v1.x = e1 * cs1 - o1 * sn1;  v1.y = e1 * sn1 + o1 * cs1;
            }
            *(float2*)(C + (size_t)r0 * N + c)       = v0;
            *(float2*)(C + (size_t)(r0 + 8) * N + c) = v1;
        }
    }
}

// ---------------------------------------------------------------------------
// Flash attention, tf32 tensor cores, register-prefetched K/V tiles.
// CTA: 128 q-rows x 1 head. 8 warps = 4(m) x 2(n); warp tile 32x32.
// ---------------------------------------------------------------------------
__global__ __launch_bounds__(256)
void attn_tf32(const float* __restrict__ q, const float* __restrict__ k,
               const float* __restrict__ v, float* __restrict__ o)
{
    extern __shared__ float sm[];
    float (*Qs)[68] = (float(*)[68])sm;                          // [128][68]
    float (*Ks)[72] = (float(*)[72])(sm + QB*68);                // [64][72]  d-major
    float (*Vs)[72] = (float(*)[72])(sm + QB*68 + 64*72);        // [64][72]  key-major
    float (*Ps)[68] = (float(*)[68])(sm + QB*68 + 2*64*72);      // [128][68]
    float2* red     = (float2*)(sm + 2*QB*68 + 2*64*72);         // [128][2]

    int b  = blockIdx.z;
    int h  = blockIdx.y;
    int qb = gridDim.x - 1 - blockIdx.x;   // heavy blocks first
    int q0 = qb * QB;
    int kvh = h >> 2;

    int tid = threadIdx.x;
    int lane = tid & 31, w = tid >> 5;
    int g = lane >> 2, tg = lane & 3;
    int wm = (w >> 1) * 32;
    int wn = w & 1;

    // load Q tile (pre-scaled by 1/8, tf32-rounded)
    {
        const float* qbase = q + (size_t)(b * Tsz + q0) * Csz + h * HD;
#pragma unroll
        for (int p = 0; p < 8; p++) {
            int i4 = tid + p * 256;
            int r = i4 >> 4, c4 = i4 & 15;
            float4 t = *(const float4*)(qbase + (size_t)r * Csz + c4 * 4);
            float4 u = make_float4(tf32r(t.x * 0.125f), tf32r(t.y * 0.125f),
                                   tf32r(t.z * 0.125f), tf32r(t.w * 0.125f));
            *(float4*)&Qs[r][c4*4] = u;
        }
    }

    float mrun[2][2], lrun[2][2];
    float oacc[2][4][4] = {};
#pragma unroll
    for (int mt = 0; mt < 2; mt++)
#pragma unroll
        for (int ri = 0; ri < 2; ri++) { mrun[mt][ri] = -1e30f; lrun[mt][ri] = 0.f; }

    float4 kreg[4], vreg[4];
    auto ldkv = [&](int kb) {
        const float* kp = k + (size_t)(b * Tsz + kb * 64) * KVC + kvh * HD;
        const float* vp = v + (size_t)(b * Tsz + kb * 64) * KVC + kvh * HD;
#pragma unroll
        for (int p = 0; p < 4; p++) {
            int idx = tid + p * 256;
            int key = idx & 63, c4 = idx >> 6;
            kreg[p] = *(const float4*)(kp + (size_t)key * KVC + c4 * 4);
            vreg[p] = *(const float4*)(vp + (size_t)key * KVC + c4 * 4);
        }
    };

    int kb_max = 2 * qb + 1;
    ldkv(0);

    for (int kb = 0; kb <= kb_max; kb++) {
        __syncthreads();   // Qs ready (first iter) / Ks,Vs,Ps consumed (later)
        // stage prefetched K (d-major) / V (key-major), tf32-rounded
#pragma unroll
        for (int p = 0; p < 4; p++) {
            int idx = tid + p * 256;
            int key = idx & 63, c4 = idx >> 6;
            Ks[c4*4+0][key] = tf32r(kreg[p].x);
            Ks[c4*4+1][key] = tf32r(kreg[p].y);
            Ks[c4*4+2][key] = tf32r(kreg[p].z);
            Ks[c4*4+3][key] = tf32r(kreg[p].w);
            float4 uu = make_float4(tf32r(vreg[p].x), tf32r(vreg[p].y),
                                    tf32r(vreg[p].z), tf32r(vreg[p].w));
            *(float4*)&Vs[key][c4*4] = uu;
        }
        __syncthreads();

        if (kb < kb_max) ldkv(kb + 1);   // overlap next tile's LDGs

        // S = Q K^T
        float s[2][4][4] = {};
#pragma unroll
        for (int ks = 0; ks < 8; ks++) {
            uint32_t af[2][4], bf[4][2];
#pragma unroll
            for (int mt = 0; mt < 2; mt++) {
                int mr = wm + mt * 16;
                af[mt][0] = __float_as_uint(Qs[mr+g  ][ks*8+tg  ]);
                af[mt][1] = __float_as_uint(Qs[mr+g+8][ks*8+tg  ]);
                af[mt][2] = __float_as_uint(Qs[mr+g  ][ks*8+tg+4]);
                af[mt][3] = __float_as_uint(Qs[mr+g+8][ks*8+tg+4]);
            }
#pragma unroll
            for (int nt = 0; nt < 4; nt++) {
                bf[nt][0] = __float_as_uint(Ks[ks*8+tg  ][wn*32+nt*8+g]);
                bf[nt][1] = __float_as_uint(Ks[ks*8+tg+4][wn*32+nt*8+g]);
            }
#pragma unroll
            for (int mt = 0; mt < 2; mt++)
#pragma unroll
                for (int nt = 0; nt < 4; nt++)
                    mma_tf32(s[mt][nt], af[mt], bf[nt]);
        }

        // causal mask (only near the diagonal)
        if (kb >= 2 * qb) {
#pragma unroll
            for (int mt = 0; mt < 2; mt++) {
                int row0 = q0 + wm + mt * 16 + g;
#pragma unroll
                for (int nt = 0; nt < 4; nt++) {
                    int col = kb * 64 + wn * 32 + nt * 8 + 2 * tg;
                    if (col     > row0    ) s[mt][nt][0] = -1e30f;
                    if (col + 1 > row0    ) s[mt][nt][1] = -1e30f;
                    if (col     > row0 + 8) s[mt][nt][2] = -1e30f;
                    if (col + 1 > row0 + 8) s[mt][nt][3] = -1e30f;
                }
            }
        }

        // per-warp-half row max + exp + sum
        float mh[2][2], sh[2][2];
#pragma unroll
        for (int mt = 0; mt < 2; mt++)
#pragma unroll
            for (int ri = 0; ri < 2; ri++) {
                float mx = -1e30f;
#pragma unroll
                for (int nt = 0; nt < 4; nt++) {
                    mx = fmaxf(mx, s[mt][nt][2*ri]);
                    mx = fmaxf(mx, s[mt][nt][2*ri+1]);
                }
                mx = fmaxf(mx, __shfl_xor_sync(0xffffffffu, mx, 1));
                mx = fmaxf(mx, __shfl_xor_sync(0xffffffffu, mx, 2));
                float sum = 0.f;
#pragma unroll
                for (int nt = 0; nt < 4; nt++) {
                    float p0 = __expf(s[mt][nt][2*ri]   - mx);
                    float p1 = __expf(s[mt][nt][2*ri+1] - mx);
                    s[mt][nt][2*ri] = p0; s[mt][nt][2*ri+1] = p1;
                    sum += p0 + p1;
                }
                sum += __shfl_xor_sync(0xffffffffu, sum, 1);
                sum += __shfl_xor_sync(0xffffffffu, sum, 2);
                mh[mt][ri] = mx; sh[mt][ri] = sum;
            }

        if (tg == 0) {
#pragma unroll
            for (int mt = 0; mt < 2; mt++)
#pragma unroll
                for (int ri = 0; ri < 2; ri++)
                    red[(wm + mt*16 + ri*8 + g) * 2 + wn] = make_float2(mh[mt][ri], sh[mt][ri]);
        }
        __syncthreads();

        // combine halves, rescale O, write P to smem
#pragma unroll
        for (int mt = 0; mt < 2; mt++)
#pragma unroll
            for (int ri = 0; ri < 2; ri++) {
                int rl = wm + mt*16 + ri*8 + g;
                float2 r0 = red[rl*2 + 0];
                float2 r1 = red[rl*2 + 1];
                float mold = mrun[mt][ri];
                float mnew = fmaxf(mold, fmaxf(r0.x, r1.x));
                float corr = __expf(mold - mnew);
                lrun[mt][ri] = lrun[mt][ri] * corr
                             + r0.y * __expf(r0.x - mnew)
                             + r1.y * __expf(r1.x - mnew);
                mrun[mt][ri] = mnew;
                float pscale = __expf(mh[mt][ri] - mnew);
#pragma unroll
                for (int nt = 0; nt < 4; nt++) {
                    oacc[mt][nt][2*ri]   *= corr;
                    oacc[mt][nt][2*ri+1] *= corr;
                    float p0 = tf32r(s[mt][nt][2*ri]   * pscale);
                    float p1 = tf32r(s[mt][nt][2*ri+1] * pscale);
                    *(float2*)&Ps[rl][wn*32 + nt*8 + 2*tg] = make_float2(p0, p1);
                }
            }
        __syncthreads();

        // O += P V
#pragma unroll
        for (int ks = 0; ks < 8; ks++) {
            uint32_t af[2][4], bf[4][2];
#pragma unroll
            for (int mt = 0; mt < 2; mt++) {
                int mr = wm + mt * 16;
                af[mt][0] = __float_as_uint(Ps[mr+g  ][ks*8+tg  ]);
                af[mt][1] = __float_as_uint(Ps[mr+g+8][ks*8+tg  ]);
                af[mt][2] = __float_as_uint(Ps[mr+g  ][ks*8+tg+4]);
                af[mt][3] = __float_as_uint(Ps[mr+g+8][ks*8+tg+4]);
            }
#pragma unroll
            for (int nt = 0; nt < 4; nt++) {
                bf[nt][0] = __float_as_uint(Vs[ks*8+tg  ][wn*32+nt*8+g]);
                bf[nt][1] = __float_as_uint(Vs[ks*8+tg+4][wn*32+nt*8+g]);
            }
#pragma unroll
            for (int mt = 0; mt < 2; mt++)
#pragma unroll
                for (int nt = 0; nt < 4; nt++)
                    mma_tf32(oacc[mt][nt], af[mt], bf[nt]);
        }
    }

    // epilogue: normalize + store
    float* obase = o + (size_t)(b * Tsz + q0) * Csz + h * HD;
#pragma unroll
    for (int mt = 0; mt < 2; mt++)
#pragma unroll
        for (int ri = 0; ri < 2; ri++) {
            int rl = wm + mt*16 + ri*8 + g;
            float inv = 1.0f / lrun[mt][ri];
#pragma unroll
            for (int nt = 0; nt < 4; nt++) {
                float2 r2 = make_float2(oacc[mt][nt][2*ri] * inv, oacc[mt][nt][2*ri+1] * inv);
                *(float2*)(obase + (size_t)rl * Csz + wn*32 + nt*8 + 2*tg) = r2;
            }
        }
}

// ---------------------------------------------------------------------------
extern "C" void kernel_launch(void* const* d_in, const int* in_sizes, int n_in,
                              void* d_out, int out_size)
{
    const float* x   = (const float*)d_in[0];
    const float* w_q = (const float*)d_in[1];
    const float* b_q = (const float*)d_in[2];
    const float* w_k = (const float*)d_in[3];
    const float* b_k = (const float*)d_in[4];
    const float* w_v = (const float*)d_in[5];
    const float* b_v = (const float*)d_in[6];
    const float* w_o = (const float*)d_in[7];
    const float* b_o = (const float*)d_in[8];
    float* out = (float*)d_out;

    float *q, *k, *v, *ao;
    cudaGetSymbolAddress((void**)&q,  g_q);
    cudaGetSymbolAddress((void**)&k,  g_k);
    cudaGetSymbolAddress((void**)&v,  g_v);
    cudaGetSymbolAddress((void**)&ao, g_ao);

    // projections (RoPE fused into Q and K epilogues)
    gemm_tf32<true ><<<dim3(Csz/64, Mrows/128), 256>>>(x, w_q, b_q, q, Mrows, Csz, Csz);
    gemm_tf32<true ><<<dim3(KVC/64, Mrows/128), 256>>>(x, w_k, b_k, k, Mrows, Csz, KVC);
    gemm_tf32<false><<<dim3(KVC/64, Mrows/128), 256>>>(x, w_v, b_v, v, Mrows, Csz, KVC);

    // flash attention
    {
        int smem = (2*QB*68 + 2*64*72 + QB*4) * (int)sizeof(float);  // 108544
        cudaFuncSetAttribute(attn_tf32, cudaFuncAttributeMaxDynamicSharedMemorySize, smem);
        attn_tf32<<<dim3(Tsz/QB, NH, Bsz), 256, smem>>>(q, k, v, ao);
    }

    // output projection
    gemm_tf32<false><<<dim3(Csz/64, Mrows/128), 256>>>(ao, w_o, b_o, out, Mrows, Csz, Csz);
}